// round 1
// baseline (speedup 1.0000x reference)
#include <cuda_runtime.h>

// AttentionConv: q,k,v = 1x1 convs; per-channel softmax over 7x7 window of
// q*(k+bias); out = sum attn*v.  B=4, C=Cout=64, H=W=64, K=7, PAD=3.
//
// Kernel 1 (qkv_kernel): three 64x64 GEMMs over 16384 pixels using packed
//   fp32x2 FMA (FFMA2). grid=(256 pixel-tiles, 3 matrices).
// Kernel 2 (attn_kernel): per (b, c, 16-row tile) block; k/v halo tile in
//   shared; register row-caching (10-wide strips serve 4 outputs x 7 taps);
//   single-pass no-max softmax via ex2.approx (safe: |log2 logit| < 128).

#define LOG2E 1.4426950408889634f

__device__ float g_q[4 * 64 * 64 * 64];
__device__ float g_k[4 * 64 * 64 * 64];
__device__ float g_v[4 * 64 * 64 * 64];

__device__ __forceinline__ float ex2f(float v) {
    float r;
    asm("ex2.approx.ftz.f32 %0, %1;" : "=f"(r) : "f"(v));
    return r;
}

__device__ __forceinline__ unsigned long long fma_f32x2(
    unsigned long long a, unsigned long long b, unsigned long long c) {
    unsigned long long d;
    asm("fma.rn.f32x2 %0, %1, %2, %3;" : "=l"(d) : "l"(a), "l"(b), "l"(c));
    return d;
}

// ---------------------------------------------------------------------------
// Kernel 1: qkv projections.
// Block: 256 threads, 64 pixels (same batch, contiguous hw), 64 out channels.
// Thread tile: 4 o x 4 p, accumulated as 2x f32x2 pairs per o.
// smem: duplicated weight pairs ws2[o][c]=(w,w) (32KB) + xs[c][p] (16KB) = 48KB.
// ---------------------------------------------------------------------------
__global__ __launch_bounds__(256) void qkv_kernel(
    const float* __restrict__ x, const float* __restrict__ y,
    const float* __restrict__ Wq, const float* __restrict__ Wk,
    const float* __restrict__ Wv) {
    __shared__ float2 ws2[64 * 64];   // 32768 B
    __shared__ float  xs[64 * 64];    // 16384 B

    const int mat = blockIdx.y;
    const float* Wsrc = (mat == 0) ? Wq : ((mat == 1) ? Wk : Wv);
    const float* src  = (mat == 2) ? y : x;
    float* dst = (mat == 0) ? g_q : ((mat == 1) ? g_k : g_v);

    const int tid = threadIdx.x;
    const int pix0 = blockIdx.x * 64;      // 64 consecutive pixels, same b
    const int b = pix0 >> 12;              // / 4096
    const int hw0 = pix0 & 4095;

#pragma unroll
    for (int i = 0; i < 16; i++) {
        int idx = tid + i * 256;           // o*64 + c
        float w = Wsrc[idx];
        ws2[idx] = make_float2(w, w);
    }
#pragma unroll
    for (int i = 0; i < 16; i++) {
        int idx = tid + i * 256;           // c*64 + p
        int c = idx >> 6, p = idx & 63;
        xs[idx] = src[((b << 6) + c) * 4096 + hw0 + p];
    }
    __syncthreads();

    const int og = tid >> 4;               // 0..15 -> o0 = og*4
    const int pg = tid & 15;               // 0..15 -> p0 = pg*4
    const int o0 = og << 2, p0 = pg << 2;

    unsigned long long acc[4][2];
#pragma unroll
    for (int i = 0; i < 4; i++) { acc[i][0] = 0ULL; acc[i][1] = 0ULL; }

#pragma unroll 16
    for (int c = 0; c < 64; c++) {
        unsigned long long x0 = *(const unsigned long long*)(xs + (c << 6) + p0);
        unsigned long long x1 = *(const unsigned long long*)(xs + (c << 6) + p0 + 2);
#pragma unroll
        for (int i = 0; i < 4; i++) {
            unsigned long long w2 =
                *(const unsigned long long*)&ws2[((o0 + i) << 6) + c];
            acc[i][0] = fma_f32x2(w2, x0, acc[i][0]);
            acc[i][1] = fma_f32x2(w2, x1, acc[i][1]);
        }
    }

#pragma unroll
    for (int i = 0; i < 4; i++) {
        float2 a0 = *reinterpret_cast<float2*>(&acc[i][0]);
        float2 a1 = *reinterpret_cast<float2*>(&acc[i][1]);
        float4 r = make_float4(a0.x, a0.y, a1.x, a1.y);
        *(float4*)(dst + ((b << 6) + o0 + i) * 4096 + hw0 + p0) = r;
    }
}

// ---------------------------------------------------------------------------
// Kernel 2: windowed per-channel softmax-attention.
// grid = (4 h-tiles, 64 channels, 4 batches); block = 256 threads.
// Block handles 16 rows x 64 cols of one (b,c) plane.
// Shared: zero-padded k/v halo tile (22 rows x 73-stride), bias[49].
// Thread: 4 outputs along w; per window-row loads 10-wide k/v strips into
// registers, serving 4 outputs x 7 taps each.
// ---------------------------------------------------------------------------
#define KSW 73

__global__ __launch_bounds__(256) void attn_kernel(
    const float* __restrict__ rel_h, const float* __restrict__ rel_w,
    float* __restrict__ out) {
    __shared__ float ks[22 * KSW];
    __shared__ float vs[22 * KSW];
    __shared__ float sbias[49];

    const int tid = threadIdx.x;
    const int h0 = blockIdx.x << 4;        // 16-row tile
    const int c  = blockIdx.y;
    const int b  = blockIdx.z;
    const int plane = ((b << 6) + c) << 12;   // (b*64+c)*4096

    // zero-fill padded tiles
    for (int i = tid; i < 22 * KSW; i += 256) { ks[i] = 0.0f; vs[i] = 0.0f; }
    if (tid < 49) {
        int kh = tid / 7, kw = tid % 7;
        sbias[tid] = (c < 32) ? rel_h[c * 7 + kh] : rel_w[(c - 32) * 7 + kw];
    }
    __syncthreads();

    // interior load: rows h0-3 .. h0+18, cols 0..63 -> padded col +3
    const float* kp = g_k + plane;
    const float* vp = g_v + plane;
    for (int i = tid; i < 22 * 64; i += 256) {
        int r = i >> 6, cc = i & 63;
        int gr = h0 - 3 + r;
        if (gr >= 0 && gr < 64) {
            ks[r * KSW + cc + 3] = kp[(gr << 6) + cc];
            vs[r * KSW + cc + 3] = vp[(gr << 6) + cc];
        }
    }
    __syncthreads();

    const int ty = tid >> 4;               // 0..15 row in tile
    const int w0 = (tid & 15) << 2;        // 4 outputs along w
    const int h = h0 + ty;

    const float4 q4 = *(const float4*)(g_q + plane + (h << 6) + w0);
    float q2[4] = {q4.x * LOG2E, q4.y * LOG2E, q4.z * LOG2E, q4.w * LOG2E};
    float s[4] = {0.f, 0.f, 0.f, 0.f};
    float a[4] = {0.f, 0.f, 0.f, 0.f};

#pragma unroll 7
    for (int hh = 0; hh < 7; hh++) {
        const float* krow = &ks[(ty + hh) * KSW + w0];
        const float* vrow = &vs[(ty + hh) * KSW + w0];
        float kr[10], vr[10];
#pragma unroll
        for (int j = 0; j < 10; j++) { kr[j] = krow[j]; vr[j] = vrow[j]; }
#pragma unroll
        for (int kw = 0; kw < 7; kw++) {
            float bb = sbias[hh * 7 + kw];
#pragma unroll
            for (int i = 0; i < 4; i++) {
                float e = ex2f(q2[i] * (kr[i + kw] + bb));
                s[i] += e;
                a[i] = fmaf(e, vr[i + kw], a[i]);
            }
        }
    }

    float4 o4;
    o4.x = __fdividef(a[0], s[0]);
    o4.y = __fdividef(a[1], s[1]);
    o4.z = __fdividef(a[2], s[2]);
    o4.w = __fdividef(a[3], s[3]);
    *(float4*)(out + plane + (h << 6) + w0) = o4;
}

extern "C" void kernel_launch(void* const* d_in, const int* in_sizes, int n_in,
                              void* d_out, int out_size) {
    const float* x     = (const float*)d_in[0];
    const float* y     = (const float*)d_in[1];
    const float* Wq    = (const float*)d_in[2];
    const float* Wk    = (const float*)d_in[3];
    const float* Wv    = (const float*)d_in[4];
    const float* rel_h = (const float*)d_in[5];
    const float* rel_w = (const float*)d_in[6];
    float* out = (float*)d_out;

    dim3 g1(256, 3, 1);
    qkv_kernel<<<g1, 256>>>(x, y, Wq, Wk, Wv);

    dim3 g2(4, 64, 4);
    attn_kernel<<<g2, 256>>>(rel_h, rel_w, out);
}